// round 17
// baseline (speedup 1.0000x reference)
#include <cuda_runtime.h>
#include <cuda_fp16.h>
#include <cstdint>
#include <math.h>

#define TOKENS  2048
#define HIDDEN  2048
#define INTER   1408
#define EXPERTS 16
#define MAXPAIRS (TOKENS*2)

// ---------------- scratch ----------------
__device__ int   g_cnt[EXPERTS];
__device__ int   g_off[EXPERTS + 1];
__device__ int   g_tok[EXPERTS * TOKENS];
__device__ float g_wslot[EXPERTS * TOKENS];
__device__ float g_logits[TOKENS * EXPERTS];

__device__ __half c_Xh[(size_t)TOKENS * HIDDEN];
__device__ __half c_Wdh[(size_t)EXPERTS * INTER * HIDDEN];
__device__ __half g_hh[(size_t)(MAXPAIRS + 128) * INTER];

// ---------------- helpers ----------------
__device__ __forceinline__ float sigmoidf_fast(float x) { return 1.0f / (1.0f + __expf(-x)); }

__device__ __forceinline__ uint32_t smem_u32(const void* p) {
    uint32_t a;
    asm("{ .reg .u64 t; cvta.to.shared.u64 t, %1; cvt.u32.u64 %0, t; }" : "=r"(a) : "l"(p));
    return a;
}
__device__ __forceinline__ uint32_t cvt2h(float x, float y) {
    __half2 h = __floats2half2_rn(x, y);
    return *(uint32_t*)&h;
}
__device__ __forceinline__ void mma16(float* d, const uint32_t* a, const uint32_t* b) {
    asm volatile("mma.sync.aligned.m16n8k16.row.col.f32.f16.f16.f32 "
        "{%0,%1,%2,%3}, {%4,%5,%6,%7}, {%8,%9}, {%0,%1,%2,%3};"
        : "+f"(d[0]), "+f"(d[1]), "+f"(d[2]), "+f"(d[3])
        : "r"(a[0]), "r"(a[1]), "r"(a[2]), "r"(a[3]), "r"(b[0]), "r"(b[1]));
}
#define LDSM4(r0,r1,r2,r3,addr) \
    asm volatile("ldmatrix.sync.aligned.m8n8.x4.shared.b16 {%0,%1,%2,%3}, [%4];" \
        : "=r"(r0), "=r"(r1), "=r"(r2), "=r"(r3) : "r"(addr))
#define LDSM4T(r0,r1,r2,r3,addr) \
    asm volatile("ldmatrix.sync.aligned.m8n8.x4.trans.shared.b16 {%0,%1,%2,%3}, [%4];" \
        : "=r"(r0), "=r"(r1), "=r"(r2), "=r"(r3) : "r"(addr))
#define CP16(dst, src, sz) \
    asm volatile("cp.async.cg.shared.global [%0], [%1], 16, %2;" \
        :: "r"(dst), "l"(src), "r"(sz) : "memory")
#define CP_COMMIT() asm volatile("cp.async.commit_group;" ::: "memory")
#define CP_WAIT1()  asm volatile("cp.async.wait_group 1;" ::: "memory")
#define CP_WAIT2()  asm volatile("cp.async.wait_group 2;" ::: "memory")
#define CP_WAIT3()  asm volatile("cp.async.wait_group 3;" ::: "memory")
#define LDS128F(v, a) \
    asm volatile("ld.shared.v4.f32 {%0,%1,%2,%3}, [%4];" \
        : "=f"((v).x), "=f"((v).y), "=f"((v).z), "=f"((v).w) : "r"(a))
#define STS128U(a, u) \
    asm volatile("st.shared.v4.b32 [%0], {%1,%2,%3,%4};" \
        :: "r"(a), "r"((u).x), "r"((u).y), "r"((u).z), "r"((u).w) : "memory")

// ---------------- conversion: fp32 -> fp16 (used for X and Wd only) ----------------
__global__ void cvt_kernel(const float* __restrict__ src,
                           __half* __restrict__ dst, int n8) {
    int i = blockIdx.x * blockDim.x + threadIdx.x;
    if (i >= n8) return;
    const float4* s = (const float4*)src + 2 * (size_t)i;
    float4 v0 = s[0], v1 = s[1];
    *(uint4*)(dst + 8 * (size_t)i) = make_uint4(
        cvt2h(v0.x, v0.y), cvt2h(v0.z, v0.w), cvt2h(v1.x, v1.y), cvt2h(v1.z, v1.w));
}

__global__ void zero_out_kernel(float* __restrict__ out) {
    int i = blockIdx.x * blockDim.x + threadIdx.x;
    *(float4*)(out + 4 * (size_t)i) = make_float4(0.f, 0.f, 0.f, 0.f);
}

// ---------------- routing (proven) ----------------
__global__ void zero_cnt_kernel() { if (threadIdx.x < EXPERTS) g_cnt[threadIdx.x] = 0; }

__global__ void router_logits_kernel(const float* __restrict__ X, const float* __restrict__ Wg) {
    int idx = blockIdx.x * blockDim.x + threadIdx.x;
    int t = idx >> 4, e = idx & 15;
    const float* xr = X + (size_t)t * HIDDEN;
    float s0 = 0.f, s1 = 0.f, s2 = 0.f, s3 = 0.f;
    #pragma unroll 4
    for (int k = 0; k < HIDDEN; k += 4) {
        s0 = fmaf(xr[k+0], Wg[(k+0)*EXPERTS + e], s0);
        s1 = fmaf(xr[k+1], Wg[(k+1)*EXPERTS + e], s1);
        s2 = fmaf(xr[k+2], Wg[(k+2)*EXPERTS + e], s2);
        s3 = fmaf(xr[k+3], Wg[(k+3)*EXPERTS + e], s3);
    }
    g_logits[idx] = (s0 + s1) + (s2 + s3);
}

__global__ void router_topk_kernel() {
    int t = blockIdx.x * blockDim.x + threadIdx.x;
    if (t >= TOKENS) return;
    float l[EXPERTS];
    #pragma unroll
    for (int e = 0; e < EXPERTS; e++) l[e] = g_logits[t * EXPERTS + e];
    int e1 = 0; float v1 = l[0];
    #pragma unroll
    for (int e = 1; e < EXPERTS; e++) if (l[e] > v1) { v1 = l[e]; e1 = e; }
    int e2 = -1; float v2 = -3.4e38f;
    #pragma unroll
    for (int e = 0; e < EXPERTS; e++) { if (e == e1) continue; if (l[e] > v2) { v2 = l[e]; e2 = e; } }
    float w1 = sigmoidf_fast(v1), w2 = sigmoidf_fast(v2);
    float inv = 1.0f / (w1 + w2); w1 *= inv; w2 *= inv;
    int s1 = atomicAdd(&g_cnt[e1], 1);
    int s2 = atomicAdd(&g_cnt[e2], 1);
    g_tok[e1 * TOKENS + s1] = t;   g_wslot[e1 * TOKENS + s1] = w1;
    g_tok[e2 * TOKENS + s2] = t;   g_wslot[e2 * TOKENS + s2] = w2;
}

__global__ void offsets_kernel() {
    if (threadIdx.x == 0 && blockIdx.x == 0) {
        int a = 0;
        for (int e = 0; e < EXPERTS; e++) { g_off[e] = a; a += g_cnt[e]; }
        g_off[EXPERTS] = a;
    }
}

// ============ FUSED gate+up GEMM with IN-KERNEL weight conversion ============
// CTA tile 128x64, BK=32, 8 warps (2m x 4n), 2 CTAs/SM.
// A = gathered c_Xh rows (fp16). W0/W1 read as fp32 via cp.async into staging,
// converted to fp16 smem one tile ahead of the MMA consumer.
__global__ __launch_bounds__(256, 2)
void moe_fused_w32(const __half* __restrict__ Agh,
                   const float* __restrict__ W0f,
                   const float* __restrict__ W1f) {
    constexpr int Kdim = HIDDEN, Ndim = INTER, KT = Kdim / 32;
    constexpr int SA  = 40;                 // A row stride (halves)
    constexpr int SBH = 72;                 // fp16 B row stride (halves)
    constexpr int STAGE_B = 10240 + 2 * 8192;        // A + B0f32 + B1f32 = 26624 B
    constexpr int OFF_B0F = 10240, OFF_B1F = 18432;  // within stage
    constexpr int BH_BASE = 3 * STAGE_B;             // 79872
    constexpr int BH_BUF  = 2 * 32 * SBH * 2;        // 9216 B (both matrices)
    constexpr int BH_MAT  = 32 * SBH * 2;            // 4608 B

    const int e  = blockIdx.z;
    const int ne = g_cnt[e];
    const int m0 = blockIdx.x * 128;
    if (m0 >= ne) return;
    const int n0  = blockIdx.y * 64;
    const int off = g_off[e];

    extern __shared__ __align__(16) char smem[];
    const uint32_t sbase = smem_u32(smem);

    const int tid  = threadIdx.x;
    const int lane = tid & 31;
    const int wid  = tid >> 5;
    const int wm   = wid & 1;
    const int wn   = wid >> 1;
    const int lg   = lane >> 2;
    const int lt   = lane & 3;
    const int q    = lane >> 3;
    const int rr   = lane & 7;

    const uint32_t a_loff = (uint32_t)(((wm * 64 + (q & 1) * 8 + rr) * SA + (q >> 1) * 8) * 2);
    const uint32_t b_loff = (uint32_t)((((q & 1) * 8 + rr) * SBH + wn * 16 + (q >> 1) * 8) * 2);

    // A cp.async: row tid>>1, halves [(tid&1)*16, +16)
    const int ar  = tid >> 1;
    const int ach = (tid & 1) * 16;
    const __half* pAh;
    uint32_t aSz;
    {
        int r = m0 + ar;
        if (r < ne) { pAh = Agh + (size_t)g_tok[e * TOKENS + r] * Kdim + ach; aSz = 16; }
        else        { pAh = Agh; aSz = 0; }
    }
    const uint32_t dA = (uint32_t)((ar * SA + ach) * 2);
    // B fp32 cp.async: row tid>>3 (0..31), floats [(tid&7)*8, +8) = 2x16B
    const int br  = tid >> 3;
    const int bc  = (tid & 7) * 8;
    const size_t bstart = (size_t)e * Kdim * Ndim + (size_t)br * Ndim + n0 + bc;
    const float* pB0 = W0f + bstart;
    const float* pB1 = W1f + bstart;
    const uint32_t dBf = (uint32_t)((br * 64 + bc) * 4);

    auto issue = [&](int kt, int buf) {
        const uint32_t st = sbase + (uint32_t)buf * STAGE_B;
        const size_t ak = (size_t)kt * 32;
        const size_t bk = (size_t)kt * 32 * Ndim;
        CP16(st + dA,                 pAh + ak,     aSz);
        CP16(st + dA + 16,            pAh + ak + 8, aSz);
        CP16(st + OFF_B0F + dBf,      pB0 + bk,     16u);
        CP16(st + OFF_B0F + dBf + 16, pB0 + bk + 4, 16u);
        CP16(st + OFF_B1F + dBf,      pB1 + bk,     16u);
        CP16(st + OFF_B1F + dBf + 16, pB1 + bk + 4, 16u);
    };
    // convert staging buf -> fp16 Bh buffer hb
    const uint32_t cvt_src = (uint32_t)((br * 64 + bc) * 4);
    const uint32_t cvt_dst = (uint32_t)((br * SBH + bc) * 2);
    auto convert = [&](int buf, int hb) {
        const uint32_t st = sbase + (uint32_t)buf * STAGE_B;
        const uint32_t dh = sbase + BH_BASE + (uint32_t)hb * BH_BUF;
        float4 v0, v1; uint4 u;
        LDS128F(v0, st + OFF_B0F + cvt_src);
        LDS128F(v1, st + OFF_B0F + cvt_src + 16);
        u = make_uint4(cvt2h(v0.x, v0.y), cvt2h(v0.z, v0.w), cvt2h(v1.x, v1.y), cvt2h(v1.z, v1.w));
        STS128U(dh + cvt_dst, u);
        LDS128F(v0, st + OFF_B1F + cvt_src);
        LDS128F(v1, st + OFF_B1F + cvt_src + 16);
        u = make_uint4(cvt2h(v0.x, v0.y), cvt2h(v0.z, v0.w), cvt2h(v1.x, v1.y), cvt2h(v1.z, v1.w));
        STS128U(dh + (uint32_t)BH_MAT + cvt_dst, u);
    };

    float accG[4][2][4], accU[4][2][4];
    #pragma unroll
    for (int i = 0; i < 4; i++)
        #pragma unroll
        for (int j = 0; j < 2; j++)
            #pragma unroll
            for (int p = 0; p < 4; p++) { accG[i][j][p] = 0.f; accU[i][j][p] = 0.f; }

    // prologue
    issue(0, 0); CP_COMMIT();
    issue(1, 1); CP_COMMIT();
    issue(2, 2); CP_COMMIT();
    CP_WAIT2();          // tile 0 arrived
    __syncthreads();     // visible
    convert(0, 0);       // Bh0 <- tile 0
    CP_WAIT1();          // tile 1 arrived
    __syncthreads();     // visible (+ Bh0 visible)

    int buf3 = 0;
    for (int kt = 0; kt < KT; kt++) {
        const uint32_t st = sbase + (uint32_t)buf3 * STAGE_B;
        const uint32_t bh = sbase + BH_BASE + (uint32_t)(kt & 1) * BH_BUF;

        #pragma unroll
        for (int ks = 0; ks < 2; ks++) {
            const uint32_t bks = (uint32_t)(ks * 16 * SBH * 2);
            uint32_t bGh[2][2], bUh[2][2];
            {
                uint32_t t0, t1, t2, t3;
                LDSM4T(t0, t1, t2, t3, bh + b_loff + bks);
                bGh[0][0]=t0; bGh[0][1]=t1; bGh[1][0]=t2; bGh[1][1]=t3;
                LDSM4T(t0, t1, t2, t3, bh + (uint32_t)BH_MAT + b_loff + bks);
                bUh[0][0]=t0; bUh[0][1]=t1; bUh[1][0]=t2; bUh[1][1]=t3;
            }
            #pragma unroll
            for (int mf = 0; mf < 4; mf++) {
                uint32_t ah[4];
                const uint32_t aa = st + a_loff + (uint32_t)(mf * 16 * SA * 2) + (uint32_t)(ks * 32);
                LDSM4(ah[0], ah[1], ah[2], ah[3], aa);
                #pragma unroll
                for (int nf = 0; nf < 2; nf++) {
                    mma16(accG[mf][nf], ah, bGh[nf]);
                    mma16(accU[mf][nf], ah, bUh[nf]);
                }
            }
        }
        // convert next tile's weights (tile kt+1 arrived & visible)
        if (kt + 1 < KT) {
            int nb = buf3 + 1; if (nb == 3) nb = 0;
            convert(nb, (kt + 1) & 1);
        }
        __syncthreads();                 // slot buf3 reads done; Bh[(kt+1)&1] written
        if (kt + 3 < KT) issue(kt + 3, buf3);
        CP_COMMIT();
        CP_WAIT1();                      // tile kt+2 arrived
        __syncthreads();                 // visible for next convert
        buf3 = (buf3 == 2) ? 0 : buf3 + 1;
    }

    // epilogue: h = silu(g)*u -> g_hh (fp16)
    #pragma unroll
    for (int mf = 0; mf < 4; mf++) {
        #pragma unroll
        for (int h = 0; h < 2; h++) {
            int r = m0 + wm * 64 + mf * 16 + lg + h * 8;
            if (r >= ne) continue;
            int col = n0 + wn * 16 + lt * 2;
            size_t base = (size_t)(off + r) * INTER + col;
            #pragma unroll
            for (int nf = 0; nf < 2; nf++) {
                float g0 = accG[mf][nf][2*h],   g1 = accG[mf][nf][2*h+1];
                float u0 = accU[mf][nf][2*h],   u1 = accU[mf][nf][2*h+1];
                float h0 = g0 * sigmoidf_fast(g0) * u0;
                float h1 = g1 * sigmoidf_fast(g1) * u1;
                *(uint32_t*)(g_hh + base + nf * 8) = cvt2h(h0, h1);
            }
        }
    }
}

// ============ down GEMM (pre-converted fp16 Wd), fused atomic combine ============
// R15 structure: 5-stage cp.async, wait_group 3, CTA 128x64, occ 2.
__global__ __launch_bounds__(256, 2)
void moe_down_fp16(const __half* __restrict__ Agh,
                   const __half* __restrict__ Bh_g,
                   float* __restrict__ outp) {
    constexpr int Kdim = INTER, Ndim = HIDDEN, KT = Kdim / 32;
    constexpr int SA = 40, SB = 72;
    constexpr int B0H = 128 * SA;
    constexpr int STAGE_H = B0H + 32 * SB;
    constexpr int STAGE_B = STAGE_H * 2;

    const int e  = blockIdx.z;
    const int ne = g_cnt[e];
    const int m0 = blockIdx.x * 128;
    if (m0 >= ne) return;
    const int n0  = blockIdx.y * 64;
    const int off = g_off[e];

    extern __shared__ __align__(16) char smem[];
    const uint32_t sbase = smem_u32(smem);

    const int tid  = threadIdx.x;
    const int lane = tid & 31;
    const int wid  = tid >> 5;
    const int wm   = wid & 1;
    const int wn   = wid >> 1;
    const int lg   = lane >> 2;
    const int lt   = lane & 3;
    const int q    = lane >> 3;
    const int rr   = lane & 7;

    const uint32_t a_loff = (uint32_t)(((wm * 64 + (q & 1) * 8 + rr) * SA + (q >> 1) * 8) * 2);
    const uint32_t b_loff = (uint32_t)((((q & 1) * 8 + rr) * SB + wn * 16 + (q >> 1) * 8) * 2);

    const int ar  = tid >> 1;
    const int ach = (tid & 1) * 16;
    const __half* pAh = Agh + (size_t)(off + m0 + ar) * Kdim + ach;
    const uint32_t dA = (uint32_t)((ar * SA + ach) * 2);
    const int br  = tid >> 3;
    const int bch = (tid & 7) * 8;
    const __half* pB = Bh_g + (size_t)e * Kdim * Ndim + (size_t)br * Ndim + n0 + bch;
    const uint32_t dB = (uint32_t)((br * SB + bch) * 2);

    auto issue = [&](int kt, int buf) {
        const uint32_t st = sbase + (uint32_t)buf * STAGE_B;
        const size_t ak = (size_t)kt * 32;
        const size_t bk = (size_t)kt * 32 * Ndim;
        CP16(st + dA,           pAh + ak,     16u);
        CP16(st + dA + 16,      pAh + ak + 8, 16u);
        CP16(st + dB + B0H * 2, pB + bk,      16u);
    };

    float accG[4][2][4];
    #pragma unroll
    for (int i = 0; i < 4; i++)
        #pragma unroll
        for (int j = 0; j < 2; j++)
            #pragma unroll
            for (int p = 0; p < 4; p++) accG[i][j][p] = 0.f;

    issue(0, 0); CP_COMMIT();
    issue(1, 1); CP_COMMIT();
    issue(2, 2); CP_COMMIT();
    issue(3, 3); CP_COMMIT();
    CP_WAIT3();
    __syncthreads();

    int buf = 0, pbuf = 4;
    for (int kt = 0; kt < KT; kt++) {
        if (kt + 4 < KT) issue(kt + 4, pbuf);
        CP_COMMIT();

        const uint32_t st = sbase + (uint32_t)buf * STAGE_B;
        #pragma unroll
        for (int ks = 0; ks < 2; ks++) {
            const uint32_t bks = (uint32_t)(ks * 16 * SB * 2);
            uint32_t bGh[2][2];
            {
                uint32_t t0, t1, t2, t3;
                LDSM4T(t0, t1, t2, t3, st + (uint32_t)(B0H * 2) + b_loff + bks);
                bGh[0][0]=t0; bGh[0][1]=t1; bGh[1][0]=t2; bGh[1][1]=t3;
            }
            #pragma unroll
            for (int mf = 0; mf < 4; mf++) {
                uint32_t ah[4];
                const uint32_t aa = st + a_loff + (uint32_t)(mf * 16 * SA * 2) + (uint32_t)(ks * 32);
                LDSM4(ah[0], ah[1], ah[2], ah[3], aa);
                #pragma unroll
                for (int nf = 0; nf < 2; nf++) mma16(accG[mf][nf], ah, bGh[nf]);
            }
        }
        CP_WAIT3();
        __syncthreads();
        buf  = (buf  == 4) ? 0 : buf + 1;
        pbuf = (pbuf == 4) ? 0 : pbuf + 1;
    }

    #pragma unroll
    for (int mf = 0; mf < 4; mf++) {
        #pragma unroll
        for (int h = 0; h < 2; h++) {
            int r = m0 + wm * 64 + mf * 16 + lg + h * 8;
            if (r >= ne) continue;
            int col = n0 + wn * 16 + lt * 2;
            int   t = g_tok[e * TOKENS + r];
            float w = g_wslot[e * TOKENS + r];
            float* orow = outp + (size_t)t * HIDDEN + col;
            #pragma unroll
            for (int nf = 0; nf < 2; nf++) {
                atomicAdd(orow + nf * 8,     w * accG[mf][nf][2*h]);
                atomicAdd(orow + nf * 8 + 1, w * accG[mf][nf][2*h+1]);
            }
        }
    }
}

// ---------------- launcher ----------------
extern "C" void kernel_launch(void* const* d_in, const int* in_sizes, int n_in,
                              void* d_out, int out_size) {
    const float* X   = (const float*)d_in[0];
    const float* Wg  = (const float*)d_in[1];
    const float* Wgp = (const float*)d_in[2];
    const float* Wup = (const float*)d_in[3];
    const float* Wdp = (const float*)d_in[4];
    float* out = (float*)d_out;

    __half *xh, *wdh, *hh;
    cudaGetSymbolAddress((void**)&xh,  c_Xh);
    cudaGetSymbolAddress((void**)&wdh, c_Wdh);
    cudaGetSymbolAddress((void**)&hh,  g_hh);

    const int SMEM_F = 3 * 26624 + 2 * 9216;          // 98304
    const int SMEM_D = 5 * ((128*40 + 32*72) * 2);    // 74240
    cudaFuncSetAttribute(moe_fused_w32, cudaFuncAttributeMaxDynamicSharedMemorySize, SMEM_F);
    cudaFuncSetAttribute(moe_down_fp16, cudaFuncAttributeMaxDynamicSharedMemorySize, SMEM_D);

    // ONE aux stream + 3 events (proven-safe footprint)
    static cudaStream_t sAux = nullptr;
    static cudaEvent_t  evFork = nullptr, evX = nullptr, evWd = nullptr;
    if (sAux == nullptr) {
        cudaStreamCreateWithFlags(&sAux, cudaStreamNonBlocking);
        cudaEventCreateWithFlags(&evFork, cudaEventDisableTiming);
        cudaEventCreateWithFlags(&evX,    cudaEventDisableTiming);
        cudaEventCreateWithFlags(&evWd,   cudaEventDisableTiming);
    }

    const int NX = TOKENS * HIDDEN / 8;
    const int NW = EXPERTS * HIDDEN * INTER / 8;

    cudaEventRecord(evFork, 0);
    cudaStreamWaitEvent(sAux, evFork, 0);

    // aux: router + X cvt, then Wd cvt (hides under the fused GEMM)
    zero_cnt_kernel<<<1, 32, 0, sAux>>>();
    router_logits_kernel<<<(TOKENS * EXPERTS) / 256, 256, 0, sAux>>>(X, Wg);
    router_topk_kernel<<<(TOKENS + 255) / 256, 256, 0, sAux>>>();
    offsets_kernel<<<1, 1, 0, sAux>>>();
    cvt_kernel<<<(NX + 255) / 256, 256, 0, sAux>>>(X, xh, NX);
    cudaEventRecord(evX, sAux);
    cvt_kernel<<<(NW + 255) / 256, 256, 0, sAux>>>(Wdp, wdh, NW);
    cudaEventRecord(evWd, sAux);

    // main: zero output, then fused GEMM directly from fp32 weights
    zero_out_kernel<<<(TOKENS * HIDDEN / 4) / 256, 256>>>(out);
    cudaStreamWaitEvent(0, evX, 0);
    dim3 grid_f(TOKENS / 128, INTER / 64, EXPERTS);    // (16, 22, 16)
    moe_fused_w32<<<grid_f, 256, SMEM_F>>>(xh, Wgp, Wup);

    // main: down GEMM with fused combine
    cudaStreamWaitEvent(0, evWd, 0);
    dim3 grid_d(TOKENS / 128, HIDDEN / 64, EXPERTS);   // (16, 32, 16)
    moe_down_fp16<<<grid_d, 256, SMEM_D>>>(hh, wdh, out);
}